// round 1
// baseline (speedup 1.0000x reference)
#include <cuda_runtime.h>

#define D_ 64
#define BM 64
#define BN 128
#define TM 4
#define TN 8
#define NT 256
#define XPAD 65   // D_+1, kills bank conflicts on scalar reads

__device__ float g_xsq[16384];
__device__ float g_wsq[8192];
__device__ float g_block_loss[512];

// ---------------------------------------------------------------------------
// prep: squared norms of inputs rows and codebook rows
// ---------------------------------------------------------------------------
__global__ void prep_kernel(const float* __restrict__ x, const float* __restrict__ w,
                            int N, int K) {
    int t = blockIdx.x * blockDim.x + threadIdx.x;
    if (t < N) {
        const float4* xr = (const float4*)(x + (size_t)t * D_);
        float s = 0.f;
#pragma unroll
        for (int i = 0; i < D_ / 4; i++) {
            float4 v = xr[i];
            s += v.x * v.x + v.y * v.y + v.z * v.z + v.w * v.w;
        }
        g_xsq[t] = s;
    }
    if (t < K) {
        const float4* wr = (const float4*)(w + (size_t)t * D_);
        float s = 0.f;
#pragma unroll
        for (int i = 0; i < D_ / 4; i++) {
            float4 v = wr[i];
            s += v.x * v.x + v.y * v.y + v.z * v.z + v.w * v.w;
        }
        g_wsq[t] = s;
    }
}

// ---------------------------------------------------------------------------
// main: argmin distance GEMM + fused gather/loss epilogue
// out layout (fp32): [0]=loss, [1 .. N*D]=quantized_st, [1+N*D .. ]=indices
// ---------------------------------------------------------------------------
__global__ __launch_bounds__(NT) void vq_main(const float* __restrict__ x,
                                              const float* __restrict__ w,
                                              float* __restrict__ out,
                                              int N, int K) {
    extern __shared__ float smem[];
    float* xs = smem;                     // BM * XPAD
    float* ws = xs + BM * XPAD;           // BN * XPAD (reused for reduction later)
    float* s_loss = ws + BN * XPAD;       // NT/32 floats

    const int t = threadIdx.x;
    const int tx = t & 15;
    const int ty = t >> 4;
    const int rowBase = blockIdx.x * BM;

    // ---- load x tile (coalesced, conflict-free stores) ----
#pragma unroll
    for (int i = 0; i < BM * D_ / NT; i++) {   // 16 per thread
        int e = t + i * NT;
        int r = e >> 6, d = e & 63;
        xs[r * XPAD + d] = x[(size_t)(rowBase + r) * D_ + d];
    }

    float xr[TM];
#pragma unroll
    for (int r = 0; r < TM; r++) xr[r] = g_xsq[rowBase + ty + 16 * r];

    float best[TM];
    int   bidx[TM];
#pragma unroll
    for (int r = 0; r < TM; r++) { best[r] = 3.4e38f; bidx[r] = 0; }

    for (int cb = 0; cb < K; cb += BN) {
        __syncthreads();   // also covers xs readiness on first iter
        // ---- load w tile: BN x D, float4 global loads ----
#pragma unroll
        for (int i = 0; i < BN * D_ / (NT * 4); i++) {  // 8 per thread
            int e4 = t + i * NT;
            int c = e4 >> 4, d4 = e4 & 15;
            float4 v = *(const float4*)(w + (size_t)(cb + c) * D_ + d4 * 4);
            float* p = ws + c * XPAD + d4 * 4;
            p[0] = v.x; p[1] = v.y; p[2] = v.z; p[3] = v.w;
        }
        __syncthreads();

        float acc[TM][TN];
#pragma unroll
        for (int r = 0; r < TM; r++)
#pragma unroll
            for (int c = 0; c < TN; c++) acc[r][c] = 0.f;

#pragma unroll 8
        for (int d = 0; d < D_; d++) {
            float a[TM], b[TN];
#pragma unroll
            for (int r = 0; r < TM; r++) a[r] = xs[(ty + 16 * r) * XPAD + d];
#pragma unroll
            for (int c = 0; c < TN; c++) b[c] = ws[(tx + 16 * c) * XPAD + d];
#pragma unroll
            for (int r = 0; r < TM; r++)
#pragma unroll
                for (int c = 0; c < TN; c++) acc[r][c] = fmaf(a[r], b[c], acc[r][c]);
        }

        // argmin update (cols increase within thread -> strict < keeps first min)
#pragma unroll
        for (int c = 0; c < TN; c++) {
            int col = cb + tx + 16 * c;
            float wq = g_wsq[col];
#pragma unroll
            for (int r = 0; r < TM; r++) {
                float dist = (xr[r] + wq) - 2.f * acc[r][c];
                if (dist < best[r]) { best[r] = dist; bidx[r] = col; }
            }
        }
    }

    // ---- cross-thread argmin reduce: reuse ws region ----
    __syncthreads();
    float* red_v = ws;                         // BM * 17
    int*   red_i = (int*)(ws + BM * 17);       // BM * 17
    int*   s_idx = (int*)(ws + 2 * BM * 17);   // BM

#pragma unroll
    for (int r = 0; r < TM; r++) {
        int row = ty + 16 * r;
        red_v[row * 17 + tx] = best[r];
        red_i[row * 17 + tx] = bidx[r];
    }
    __syncthreads();

    if (t < BM) {
        float bv = red_v[t * 17 + 0];
        int   bi = red_i[t * 17 + 0];
#pragma unroll
        for (int j = 1; j < 16; j++) {
            float v = red_v[t * 17 + j];
            int   ii = red_i[t * 17 + j];
            if (v < bv || (v == bv && ii < bi)) { bv = v; bi = ii; }
        }
        s_idx[t] = bi;
        out[1 + (size_t)N * D_ + rowBase + t] = (float)bi;
    }
    __syncthreads();

    // ---- quantized gather + loss partial (coalesced stores) ----
    float lsum = 0.f;
#pragma unroll
    for (int i = 0; i < BM * D_ / NT; i++) {
        int e = t + i * NT;
        int r = e >> 6, d = e & 63;
        float q = w[(size_t)s_idx[r] * D_ + d];
        out[1 + (size_t)(rowBase + r) * D_ + d] = q;
        float df = q - xs[r * XPAD + d];
        lsum += df * df;
    }
#pragma unroll
    for (int o = 16; o > 0; o >>= 1) lsum += __shfl_down_sync(0xffffffffu, lsum, o);
    if ((t & 31) == 0) s_loss[t >> 5] = lsum;
    __syncthreads();
    if (t == 0) {
        float s = 0.f;
#pragma unroll
        for (int wI = 0; wI < NT / 32; wI++) s += s_loss[wI];
        g_block_loss[blockIdx.x] = s;   // deterministic (no atomics)
    }
}

// ---------------------------------------------------------------------------
// finalize: loss = (1 + 0.25) * mean((q - x)^2)
// ---------------------------------------------------------------------------
__global__ void finalize_kernel(float* __restrict__ out, int nblocks, int total) {
    __shared__ float sm[256];
    float s = 0.f;
    for (int i = threadIdx.x; i < nblocks; i += 256) s += g_block_loss[i];
    sm[threadIdx.x] = s;
    __syncthreads();
    for (int o = 128; o > 0; o >>= 1) {
        if (threadIdx.x < o) sm[threadIdx.x] += sm[threadIdx.x + o];
        __syncthreads();
    }
    if (threadIdx.x == 0) out[0] = 1.25f * sm[0] / (float)total;
}

// ---------------------------------------------------------------------------
extern "C" void kernel_launch(void* const* d_in, const int* in_sizes, int n_in,
                              void* d_out, int out_size) {
    const float* x = (const float*)d_in[0];
    const float* w = (const float*)d_in[1];
    float* out = (float*)d_out;

    int N = in_sizes[0] / D_;   // 16384
    int K = in_sizes[1] / D_;   // 8192

    int maxNK = N > K ? N : K;
    prep_kernel<<<(maxNK + NT - 1) / NT, NT>>>(x, w, N, K);

    int smem_bytes = (BM * XPAD + BN * XPAD + NT / 32) * (int)sizeof(float);
    cudaFuncSetAttribute(vq_main, cudaFuncAttributeMaxDynamicSharedMemorySize, smem_bytes);
    int nb = N / BM;   // 256 blocks
    vq_main<<<nb, NT, smem_bytes>>>(x, w, out, N, K);

    finalize_kernel<<<1, 256>>>(out, nb, N * D_);
}

// round 3
// speedup vs baseline: 1.0415x; 1.0415x over previous
#include <cuda_runtime.h>
#include <stdint.h>

#define D_   64
#define NROW 16384
#define KCB  8192
#define BM   128
#define BN   256
#define NT   256
#define KT   (KCB / BN)      // 32 tiles
#define CAP  256
#define WPITCH 68            // 68 mod 32 = 4 -> conflict-free frag reads

__device__ float g_xsq[NROW];
__device__ float g_wsq[KCB];
__device__ float g_wmax;
__device__ int   g_cnt[NROW];
__device__ int   g_cand[NROW * CAP];
__device__ float g_rowloss[NROW];

// ---------------------------------------------------------------------------
__device__ __forceinline__ void cp16(uint32_t dst, const void* src) {
    asm volatile("cp.async.cg.shared.global [%0], [%1], 16;\n" :: "r"(dst), "l"(src));
}
__device__ __forceinline__ void cp4(uint32_t dst, const void* src) {
    asm volatile("cp.async.ca.shared.global [%0], [%1], 4;\n" :: "r"(dst), "l"(src));
}
__device__ __forceinline__ void cp_commit() { asm volatile("cp.async.commit_group;\n"); }
__device__ __forceinline__ void cp_wait1()  { asm volatile("cp.async.wait_group 1;\n"); }
__device__ __forceinline__ void cp_wait0()  { asm volatile("cp.async.wait_group 0;\n"); }

__device__ __forceinline__ void mma_tf32(float (&c)[4], const float (&a)[4], const float (&b)[2]) {
    asm volatile(
        "mma.sync.aligned.m16n8k8.row.col.f32.tf32.tf32.f32 "
        "{%0,%1,%2,%3},{%4,%5,%6,%7},{%8,%9},{%0,%1,%2,%3};\n"
        : "+f"(c[0]), "+f"(c[1]), "+f"(c[2]), "+f"(c[3])
        : "r"(__float_as_uint(a[0])), "r"(__float_as_uint(a[1])),
          "r"(__float_as_uint(a[2])), "r"(__float_as_uint(a[3])),
          "r"(__float_as_uint(b[0])), "r"(__float_as_uint(b[1])));
}

// ---------------------------------------------------------------------------
// prep: xsq, wsq, zero candidate counters
// ---------------------------------------------------------------------------
__global__ void prep_kernel(const float* __restrict__ x, const float* __restrict__ w) {
    int t = blockIdx.x * blockDim.x + threadIdx.x;
    if (t < NROW) {
        const float4* xr = (const float4*)(x + (size_t)t * D_);
        float s = 0.f;
#pragma unroll
        for (int i = 0; i < D_ / 4; i++) {
            float4 v = xr[i];
            s += v.x * v.x + v.y * v.y + v.z * v.z + v.w * v.w;
        }
        g_xsq[t] = s;
        g_cnt[t] = 0;
    }
    if (t < KCB) {
        const float4* wr = (const float4*)(w + (size_t)t * D_);
        float s = 0.f;
#pragma unroll
        for (int i = 0; i < D_ / 4; i++) {
            float4 v = wr[i];
            s += v.x * v.x + v.y * v.y + v.z * v.z + v.w * v.w;
        }
        g_wsq[t] = s;
    }
}

__global__ void wmax_kernel() {
    __shared__ float sm[256];
    float m = 0.f;
    for (int i = threadIdx.x; i < KCB; i += 256) m = fmaxf(m, g_wsq[i]);
    sm[threadIdx.x] = m;
    __syncthreads();
    for (int o = 128; o > 0; o >>= 1) {
        if (threadIdx.x < o) sm[threadIdx.x] = fmaxf(sm[threadIdx.x], sm[threadIdx.x + o]);
        __syncthreads();
    }
    if (threadIdx.x == 0) g_wmax = sm[0];
}

// ---------------------------------------------------------------------------
// main: TF32 tensor-core distance GEMM; emits candidate (row, col) pairs
// ---------------------------------------------------------------------------
__global__ __launch_bounds__(NT, 1) void vq_mma(const float* __restrict__ x,
                                                const float* __restrict__ w) {
    extern __shared__ float sm[];
    float* xs   = sm;                       // 128 * 68
    float* ws   = xs + BM * WPITCH;         // 2 * 256 * 68 (double buffer)
    float* wsqs = ws + 2 * BN * WPITCH;     // 2 * 256

    const int tid  = threadIdx.x;
    const int lane = tid & 31;
    const int wid  = tid >> 5;
    const int wm   = wid >> 2;   // 0..1  (m direction)
    const int wn   = wid & 3;    // 0..3  (n direction)
    const int rowBase = blockIdx.x * BM;

    // ---- load x tile (fp32, padded pitch) ----
#pragma unroll
    for (int i = 0; i < 8; i++) {
        int idx = tid + i * NT;              // over 2048 float4
        int r = idx >> 4, q = idx & 15;
        float4 v = *(const float4*)(x + (size_t)(rowBase + r) * D_ + q * 4);
        *(float4*)(xs + r * WPITCH + q * 4) = v;
    }

    // ---- per-thread owned rows ----
    float xq[8], bnd[8], gmin[8];
    int   rowid[8];
    const float bndc = 0.03125f * sqrtf(g_wmax);   // 2^-5 * ||w||max
#pragma unroll
    for (int mf = 0; mf < 4; mf++)
#pragma unroll
        for (int hi = 0; hi < 2; hi++) {
            int slot = mf * 2 + hi;
            int r = rowBase + wm * 64 + mf * 16 + (lane >> 2) + hi * 8;
            rowid[slot] = r;
            float q = g_xsq[r];
            xq[slot]  = q;
            bnd[slot] = bndc * sqrtf(q);
            gmin[slot] = 1e30f;
        }

    // ---- cp.async issue of codebook tile t into buffer b ----
    auto issue_tile = [&](int t, int b) {
        const float* wsrc = w + (size_t)t * BN * D_;
        float* wdst = ws + b * BN * WPITCH;
#pragma unroll
        for (int i = 0; i < 16; i++) {
            int idx = tid + i * NT;          // over 4096 float4
            int r = idx >> 4, q = idx & 15;
            cp16((uint32_t)__cvta_generic_to_shared(wdst + r * WPITCH + q * 4),
                 wsrc + (size_t)r * D_ + q * 4);
        }
        cp4((uint32_t)__cvta_generic_to_shared(wsqs + b * BN + tid), g_wsq + t * BN + tid);
    };

    issue_tile(0, 0);
    cp_commit();

    for (int t = 0; t < KT; t++) {
        const int buf = t & 1;
        if (t + 1 < KT) {
            issue_tile(t + 1, (t + 1) & 1);
            cp_commit();
            cp_wait1();
        } else {
            cp_wait0();
        }
        __syncthreads();

        const float* wt = ws + buf * BN * WPITCH;
        const float* wq = wsqs + buf * BN;

        float C[4][8][4];
#pragma unroll
        for (int mf = 0; mf < 4; mf++)
#pragma unroll
            for (int nf = 0; nf < 8; nf++)
#pragma unroll
                for (int q = 0; q < 4; q++) C[mf][nf][q] = 0.f;

#pragma unroll
        for (int kk = 0; kk < 8; kk++) {
            const int k0 = kk * 8 + (lane & 3);
            float a[4][4];
#pragma unroll
            for (int mf = 0; mf < 4; mf++) {
                int r0 = wm * 64 + mf * 16 + (lane >> 2);
                a[mf][0] = xs[r0 * WPITCH + k0];
                a[mf][1] = xs[(r0 + 8) * WPITCH + k0];
                a[mf][2] = xs[r0 * WPITCH + k0 + 4];
                a[mf][3] = xs[(r0 + 8) * WPITCH + k0 + 4];
            }
            float b[8][2];
#pragma unroll
            for (int nf = 0; nf < 8; nf++) {
                int cc = wn * 64 + nf * 8 + (lane >> 2);
                b[nf][0] = wt[cc * WPITCH + k0];
                b[nf][1] = wt[cc * WPITCH + k0 + 4];
            }
#pragma unroll
            for (int mf = 0; mf < 4; mf++)
#pragma unroll
                for (int nf = 0; nf < 8; nf++) mma_tf32(C[mf][nf], a[mf], b[nf]);
        }

        // ---- epilogue: distance, running min, candidate append ----
        const int tileBase = t * BN;
#pragma unroll
        for (int nf = 0; nf < 8; nf++) {
            int cl = wn * 64 + nf * 8 + (lane & 3) * 2;
            float w0 = wq[cl], w1 = wq[cl + 1];
            int colb = tileBase + cl;
#pragma unroll
            for (int mf = 0; mf < 4; mf++)
#pragma unroll
                for (int hi = 0; hi < 2; hi++) {
                    int slot = mf * 2 + hi;
                    float d0 = fmaf(-2.f, C[mf][nf][hi * 2 + 0], xq[slot] + w0);
                    float d1 = fmaf(-2.f, C[mf][nf][hi * 2 + 1], xq[slot] + w1);
                    float thr = gmin[slot] + bnd[slot];
                    if (d0 < thr) {
                        int s = atomicAdd(&g_cnt[rowid[slot]], 1);
                        if (s < CAP) g_cand[rowid[slot] * CAP + s] = colb;
                    }
                    if (d1 < thr) {
                        int s = atomicAdd(&g_cnt[rowid[slot]], 1);
                        if (s < CAP) g_cand[rowid[slot] * CAP + s] = colb + 1;
                    }
                    float m = fminf(d0, d1);
                    gmin[slot] = fminf(gmin[slot], m);
                }
        }
        // tighten: combine mins across the 4 lanes sharing each row
#pragma unroll
        for (int slot = 0; slot < 8; slot++) {
            float v = gmin[slot];
            v = fminf(v, __shfl_xor_sync(0xffffffffu, v, 1));
            v = fminf(v, __shfl_xor_sync(0xffffffffu, v, 2));
            gmin[slot] = v;
        }
        __syncthreads();
    }
}

// ---------------------------------------------------------------------------
// rescore: exact fp32 argmin over candidates; writes quantized/index/loss
// out layout: [0]=loss, [1 .. N*D]=quantized, [1+N*D ..]=indices (as float)
// NOTE: quantized region starts at out+1 (4B-aligned only) -> SCALAR stores.
// ---------------------------------------------------------------------------
__global__ __launch_bounds__(256) void rescore_kernel(const float* __restrict__ x,
                                                      const float* __restrict__ w,
                                                      float* __restrict__ out) {
    int gw   = (blockIdx.x * blockDim.x + threadIdx.x) >> 5;
    int lane = threadIdx.x & 31;
    if (gw >= NROW) return;
    const int row = gw;

    int cnt = g_cnt[row];
    if (cnt > CAP) cnt = CAP;

    float2 xv = ((const float2*)(x + (size_t)row * D_))[lane];
    float  xq = g_xsq[row];

    float bd = 3.4e38f;
    int   bc = 0x7fffffff;
    for (int i = 0; i < cnt; i++) {
        int col = g_cand[row * CAP + i];
        float2 wv = ((const float2*)(w + (size_t)col * D_))[lane];
        float p = xv.x * wv.x + xv.y * wv.y;
#pragma unroll
        for (int o = 16; o > 0; o >>= 1) p += __shfl_xor_sync(0xffffffffu, p, o);
        float d = xq + g_wsq[col] - 2.f * p;
        if (d < bd || (d == bd && col < bc)) { bd = d; bc = col; }
    }

    float2 wv = ((const float2*)(w + (size_t)bc * D_))[lane];
    float* qo = out + 1 + (size_t)row * D_ + lane * 2;   // 4B-aligned region
    qo[0] = wv.x;
    qo[1] = wv.y;
    if (lane == 0) out[1 + (size_t)NROW * D_ + row] = (float)bc;

    float dx = wv.x - xv.x, dy = wv.y - xv.y;
    float l = dx * dx + dy * dy;
#pragma unroll
    for (int o = 16; o > 0; o >>= 1) l += __shfl_xor_sync(0xffffffffu, l, o);
    if (lane == 0) g_rowloss[row] = l;
}

// ---------------------------------------------------------------------------
__global__ void finalize_kernel(float* __restrict__ out) {
    __shared__ float sm[256];
    float s = 0.f;
    for (int i = threadIdx.x; i < NROW; i += 256) s += g_rowloss[i];
    sm[threadIdx.x] = s;
    __syncthreads();
    for (int o = 128; o > 0; o >>= 1) {
        if (threadIdx.x < o) sm[threadIdx.x] += sm[threadIdx.x + o];
        __syncthreads();
    }
    if (threadIdx.x == 0) out[0] = 1.25f * sm[0] / (float)(NROW * D_);
}

// ---------------------------------------------------------------------------
extern "C" void kernel_launch(void* const* d_in, const int* in_sizes, int n_in,
                              void* d_out, int out_size) {
    const float* x = (const float*)d_in[0];
    const float* w = (const float*)d_in[1];
    float* out = (float*)d_out;

    prep_kernel<<<(NROW + NT - 1) / NT, NT>>>(x, w);
    wmax_kernel<<<1, 256>>>();

    int smem_bytes = (BM * WPITCH + 2 * BN * WPITCH + 2 * BN) * (int)sizeof(float);
    cudaFuncSetAttribute(vq_mma, cudaFuncAttributeMaxDynamicSharedMemorySize, smem_bytes);
    vq_mma<<<NROW / BM, NT, smem_bytes>>>(x, w);

    rescore_kernel<<<NROW / 8, 256>>>(x, w, out);
    finalize_kernel<<<1, 256>>>(out);
}